// round 2
// baseline (speedup 1.0000x reference)
#include <cuda_runtime.h>

#define NTOK 4096
#define DIM  512
#define H    12
#define ZD   64
#define HZ   768
#define RP   33
#define CP   17

__device__ float g_Qp[NTOK*HZ];
__device__ float g_Kp[NTOK*HZ];
__device__ float g_dQ[NTOK*HZ];
__device__ float g_dK[NTOK*HZ];
__device__ float g_LSE[NTOK*H];

__device__ __forceinline__ float fexp(float x){
    x = fminf(fmaxf(x,-87.f),87.f);
    float n = rintf(x*1.4426950408889634f);
    float g = fmaf(n,-0.69314718055994531f,x);
    float p = 1.3888889e-3f;
    p = fmaf(p,g,8.3333333e-3f);
    p = fmaf(p,g,4.1666667e-2f);
    p = fmaf(p,g,1.6666667e-1f);
    p = fmaf(p,g,0.5f);
    p = fmaf(p,g,1.f);
    p = fmaf(p,g,1.f);
    return p*__int_as_float(((int)n+127)<<23);
}

// out[n,hz] = sum_d A[n,d]*W[hz,d] + B[hz]
__global__ void __launch_bounds__(256) proj_kernel(const float* __restrict__ A,
                                                   const float* __restrict__ W,
                                                   const float* __restrict__ Bv,
                                                   int sel){
    float* out = sel ? g_Kp : g_Qp;
    __shared__ float As[16][68];
    __shared__ float Ws[16][68];
    const int tid = threadIdx.x;
    const int tx = tid & 15, ty = tid >> 4;
    const int n0 = blockIdx.y*64, j0 = blockIdx.x*64;
    const int lr = tid >> 2, lc = (tid & 3) << 2;
    float acc[4][4] = {};
    for(int d0 = 0; d0 < DIM; d0 += 16){
        float4 va = *(const float4*)&A[(n0+lr)*DIM + d0 + lc];
        float4 vw = *(const float4*)&W[(j0+lr)*DIM + d0 + lc];
        __syncthreads();
        As[lc+0][lr]=va.x; As[lc+1][lr]=va.y; As[lc+2][lr]=va.z; As[lc+3][lr]=va.w;
        Ws[lc+0][lr]=vw.x; Ws[lc+1][lr]=vw.y; Ws[lc+2][lr]=vw.z; Ws[lc+3][lr]=vw.w;
        __syncthreads();
#pragma unroll
        for(int kd = 0; kd < 16; kd++){
            float av[4], bv[4];
#pragma unroll
            for(int i=0;i<4;i++) av[i]=As[kd][ty*4+i];
#pragma unroll
            for(int j=0;j<4;j++) bv[j]=Ws[kd][tx*4+j];
#pragma unroll
            for(int i=0;i<4;i++)
#pragma unroll
                for(int j=0;j<4;j++) acc[i][j]=fmaf(av[i],bv[j],acc[i][j]);
        }
    }
#pragma unroll
    for(int i=0;i<4;i++)
#pragma unroll
        for(int j=0;j<4;j++)
            out[(n0+ty*4+i)*HZ + j0+tx*4+j] = acc[i][j] + Bv[j0+tx*4+j];
}

// MODE 0: forward LSE.  MODE 1: dQ (rows=q).  MODE 2: dK (rows=k).
template<int MODE>
__global__ void __launch_bounds__(384) pass_kernel(const float* __restrict__ adj,
                                                   const float* __restrict__ Hw,
                                                   const float* __restrict__ betas){
    extern __shared__ float sm[];
    float* Rt = sm;                  // [HZ][RP]
    float* Ct = Rt + HZ*RP;          // [HZ][CP]
    float* ss = Ct + HZ*CP;          // [H][32][CP]
    float* base = ss + H*32*CP;
    float* psb  = base;              // [H][32][CP] (bwd only)
    float* adjs = (MODE==0) ? base : base + H*32*CP;  // [32][CP]
    float* lses = adjs + 32*CP;      // [16][H] (MODE 2)

    const int tid = threadIdx.x;
    const int w = tid >> 5, l = tid & 31;
    const int rb = blockIdx.x * 32;
    const float* Rg = (MODE==2) ? g_Kp : g_Qp;
    const float* Cg = (MODE==2) ? g_Qp : g_Kp;

    float C2r[H], D2r[H];
    const float bw = betas[w];
#pragma unroll
    for(int h=0; h<H; h++){
        C2r[h] = betas[h]*Hw[h*H + w];
        if(MODE) D2r[h] = bw*Hw[w*H + h]*(-1.f/betas[h]);
    }
    float lse_reg = 0.f;
    if(MODE==1) lse_reg = g_LSE[(rb+l)*H + w];

    for(int idx = tid; idx < 32*192; idx += 384){
        int r = idx/192, c4 = (idx%192)<<2;
        float4 v = *(const float4*)&Rg[(rb+r)*HZ + c4];
        Rt[(c4+0)*RP+r]=v.x; Rt[(c4+1)*RP+r]=v.y; Rt[(c4+2)*RP+r]=v.z; Rt[(c4+3)*RP+r]=v.w;
    }

    const int rg=l>>2, sub=l&3, r0=rg<<2, c0=sub<<2, z0=sub<<4;
    float m = -1e30f, lsum = 0.f;
    float dacc[4][16] = {};

    for(int cc = 0; cc < NTOK; cc += 16){
        __syncthreads();
        for(int idx = tid; idx < 16*192; idx += 384){
            int c = idx/192, c4 = (idx%192)<<2;
            float4 v = *(const float4*)&Cg[(cc+c)*HZ + c4];
            Ct[(c4+0)*CP+c]=v.x; Ct[(c4+1)*CP+c]=v.y; Ct[(c4+2)*CP+c]=v.z; Ct[(c4+3)*CP+c]=v.w;
        }
        if(MODE==2){
            for(int idx = tid; idx < 512; idx += 384){
                int c = idx>>5, kk = idx&31;
                adjs[kk*CP + c] = adj[(cc+c)*NTOK + rb + kk];
            }
            for(int idx = tid; idx < 16*H; idx += 384)
                lses[idx] = g_LSE[(cc + idx/H)*H + (idx%H)];
        } else {
            for(int idx = tid; idx < 512; idx += 384){
                int q = idx>>4, k = idx&15;
                adjs[q*CP + k] = adj[(rb+q)*NTOK + cc + k];
            }
        }
        __syncthreads();

        // scores: warp w = head, 4r x 4c per thread
        float acc[4][4] = {};
#pragma unroll 8
        for(int z = 0; z < ZD; z++){
            int hz = w*ZD + z;
            float av[4], bv[4];
#pragma unroll
            for(int i=0;i<4;i++) av[i] = Rt[hz*RP + r0 + i];
#pragma unroll
            for(int j=0;j<4;j++) bv[j] = Ct[hz*CP + c0 + j];
#pragma unroll
            for(int i=0;i<4;i++)
#pragma unroll
                for(int j=0;j<4;j++) acc[i][j]=fmaf(av[i],bv[j],acc[i][j]);
        }
#pragma unroll
        for(int i=0;i<4;i++)
#pragma unroll
            for(int j=0;j<4;j++) ss[(w*32 + r0+i)*CP + c0+j] = acc[i][j];
        __syncthreads();

        // mix: warp w = hp, lane l = row
#pragma unroll 4
        for(int k = 0; k < 16; k++){
            float a = 0.f;
#pragma unroll
            for(int h=0; h<H; h++) a = fmaf(C2r[h], ss[(h*32+l)*CP + k], a);
            float ad = adjs[l*CP + k];
            if(MODE==0){
                if(ad != 0.f){
                    if(a <= m) lsum += fexp(a - m);
                    else { lsum = fmaf(lsum, fexp(m - a), 1.f); m = a; }
                }
            } else {
                float lse = (MODE==1) ? lse_reg : lses[k*H + w];
                psb[(w*32+l)*CP + k] = (ad != 0.f) ? fexp(a - lse) : 0.f;
            }
        }
        if(MODE){
            __syncthreads();
#pragma unroll 4
            for(int k = 0; k < 16; k++){
                float s2 = 0.f;
#pragma unroll
                for(int hp=0; hp<H; hp++) s2 = fmaf(D2r[hp], psb[(hp*32+l)*CP + k], s2);
                ss[(w*32+l)*CP + k] = s2;
            }
            __syncwarp();
            for(int k = 0; k < 16; k++){
                float w2v[4];
#pragma unroll
                for(int i=0;i<4;i++) w2v[i] = ss[(w*32 + r0+i)*CP + k];
#pragma unroll
                for(int zi=0; zi<16; zi++){
                    float cv = Ct[(w*ZD + z0 + zi)*CP + k];
#pragma unroll
                    for(int i=0;i<4;i++) dacc[i][zi] = fmaf(w2v[i], cv, dacc[i][zi]);
                }
            }
        }
    }

    if(MODE==0){
        float lse = (lsum > 0.f) ? (m + logf(lsum)) : 0.f;
        g_LSE[(rb+l)*H + w] = lse;
    } else {
        float* dst = (MODE==1) ? g_dQ : g_dK;
#pragma unroll
        for(int i=0;i<4;i++){
            float* p = &dst[(rb + r0 + i)*HZ + w*ZD + z0];
#pragma unroll
            for(int zz=0; zz<16; zz+=4)
                *(float4*)&p[zz] = make_float4(dacc[i][zz],dacc[i][zz+1],dacc[i][zz+2],dacc[i][zz+3]);
        }
    }
}

__global__ void energy_kernel(const float* __restrict__ betas, float* __restrict__ out){
    __shared__ double red[256];
    const int tid = threadIdx.x;
    double a = 0.0;
    for(int i = tid; i < NTOK*H; i += 256)
        a += (double)g_LSE[i] * (-1.0/(double)betas[i % H]);
    red[tid] = a;
    __syncthreads();
    for(int s = 128; s > 0; s >>= 1){
        if(tid < s) red[tid] += red[tid + s];
        __syncthreads();
    }
    if(tid == 0) out[0] = (float)red[0];
}

// dG[n,d] = sum_hz dQ[n,hz]*Wq[hz,d] + dK[n,hz]*Wk[hz,d]
__global__ void __launch_bounds__(256) grad_kernel(const float* __restrict__ Wq,
                                                   const float* __restrict__ Wk,
                                                   float* __restrict__ out){
    __shared__ float Aq[16][68], Ak[16][68], Bq[16][68], Bk[16][68];
    const int tid = threadIdx.x;
    const int n0 = blockIdx.y*64, d0 = blockIdx.x*64;
    const int tx = tid & 15, ty = tid >> 4;
    const int lr = tid >> 2, lc = (tid & 3) << 2;
    const int wr = tid >> 4, wc = (tid & 15) << 2;
    float acc[4][4] = {};
    for(int h0 = 0; h0 < HZ; h0 += 16){
        float4 va = *(const float4*)&g_dQ[(n0+lr)*HZ + h0 + lc];
        float4 vk = *(const float4*)&g_dK[(n0+lr)*HZ + h0 + lc];
        float4 wq = *(const float4*)&Wq[(h0+wr)*DIM + d0 + wc];
        float4 wk = *(const float4*)&Wk[(h0+wr)*DIM + d0 + wc];
        __syncthreads();
        Aq[lc+0][lr]=va.x; Aq[lc+1][lr]=va.y; Aq[lc+2][lr]=va.z; Aq[lc+3][lr]=va.w;
        Ak[lc+0][lr]=vk.x; Ak[lc+1][lr]=vk.y; Ak[lc+2][lr]=vk.z; Ak[lc+3][lr]=vk.w;
        *(float4*)&Bq[wr][wc] = wq;
        *(float4*)&Bk[wr][wc] = wk;
        __syncthreads();
#pragma unroll
        for(int kd = 0; kd < 16; kd++){
            float aq[4], ak[4], bq[4], bk[4];
#pragma unroll
            for(int i=0;i<4;i++){ aq[i]=Aq[kd][ty*4+i]; ak[i]=Ak[kd][ty*4+i]; }
#pragma unroll
            for(int j=0;j<4;j++){ bq[j]=Bq[kd][tx*4+j]; bk[j]=Bk[kd][tx*4+j]; }
#pragma unroll
            for(int i=0;i<4;i++)
#pragma unroll
                for(int j=0;j<4;j++){
                    acc[i][j]=fmaf(aq[i],bq[j],acc[i][j]);
                    acc[i][j]=fmaf(ak[i],bk[j],acc[i][j]);
                }
        }
    }
#pragma unroll
    for(int i=0;i<4;i++)
#pragma unroll
        for(int j=0;j<4;j++)
            out[1 + (n0+ty*4+i)*DIM + d0+tx*4+j] = acc[i][j];
}

extern "C" void kernel_launch(void* const* d_in, const int* in_sizes, int n_in,
                              void* d_out, int out_size){
    const float* g    = (const float*)d_in[0];
    const float* adj  = (const float*)d_in[1];
    const float* Wk   = (const float*)d_in[2];
    const float* Wq   = (const float*)d_in[3];
    const float* Hw   = (const float*)d_in[4];
    const float* Bk   = (const float*)d_in[5];
    const float* Bq   = (const float*)d_in[6];
    const float* betas= (const float*)d_in[7];
    float* out = (float*)d_out;

    const int SM0 = (HZ*RP + HZ*CP + H*32*CP + 32*CP) * 4;
    const int SM1 = SM0 + H*32*CP*4;
    const int SM2 = SM1 + 16*H*4;
    cudaFuncSetAttribute(pass_kernel<0>, cudaFuncAttributeMaxDynamicSharedMemorySize, SM0);
    cudaFuncSetAttribute(pass_kernel<1>, cudaFuncAttributeMaxDynamicSharedMemorySize, SM1);
    cudaFuncSetAttribute(pass_kernel<2>, cudaFuncAttributeMaxDynamicSharedMemorySize, SM2);

    proj_kernel<<<dim3(HZ/64, NTOK/64), 256>>>(g, Wq, Bq, 0);
    proj_kernel<<<dim3(HZ/64, NTOK/64), 256>>>(g, Wk, Bk, 1);
    pass_kernel<0><<<NTOK/32, 384, SM0>>>(adj, Hw, betas);
    energy_kernel<<<1, 256>>>(betas, out);
    pass_kernel<1><<<NTOK/32, 384, SM1>>>(adj, Hw, betas);
    pass_kernel<2><<<NTOK/32, 384, SM2>>>(adj, Hw, betas);
    grad_kernel<<<dim3(DIM/64, NTOK/64), 256>>>(Wq, Wk, out);
}